// round 4
// baseline (speedup 1.0000x reference)
#include <cuda_runtime.h>
#include <cstdint>

#define SLEN 1024
#define BSZ  16
#define IND  256
#define NH   8
#define DH   32
#define PROJ 776              // NH*(3*DH+1)
#define NTOK (SLEN*BSZ)       // 16384
#define NCHAIN (BSZ*NH)       // 128
#define FW_ELEMS (NCHAIN*DH*DH)
#define TC   16               // time chunk in recurrence

// Scratch (static device globals; no runtime allocation)
__device__ float g_normed[(size_t)NTOK*IND];
__device__ float g_qkvb[(size_t)NTOK*PROJ];
__device__ float g_oseq[(size_t)NTOK*IND];
// chain-major prepped streams: [chain][t][lane]
__device__ float g_kn[(size_t)NCHAIN*SLEN*DH];
__device__ float g_qn[(size_t)NCHAIN*SLEN*DH];
__device__ float g_vn[(size_t)NCHAIN*SLEN*DH];
__device__ float g_sc[(size_t)NCHAIN*SLEN*2];   // (beta, k.q)

// ---------------------------------------------------------------------------
// Packed f32x2 helpers (Blackwell)
// ---------------------------------------------------------------------------
typedef unsigned long long u64t;

__device__ __forceinline__ u64t f2pack(float lo, float hi) {
    u64t r;
    asm("mov.b64 %0, {%1, %2};" : "=l"(r) : "f"(lo), "f"(hi));
    return r;
}
__device__ __forceinline__ void f2unpack(u64t v, float& lo, float& hi) {
    asm("mov.b64 {%0, %1}, %2;" : "=f"(lo), "=f"(hi) : "l"(v));
}
__device__ __forceinline__ u64t ffma2(u64t a, u64t b, u64t c) {
    u64t d;
    asm("fma.rn.f32x2 %0, %1, %2, %3;" : "=l"(d) : "l"(a), "l"(b), "l"(c));
    return d;
}

// ---------------------------------------------------------------------------
// LayerNorm: one block (256 threads) per token row
// ---------------------------------------------------------------------------
__global__ void ln_kernel(const float* __restrict__ x,
                          const float* __restrict__ gamma,
                          const float* __restrict__ beta)
{
    int row = blockIdx.x;
    int tid = threadIdx.x;
    float v = x[(size_t)row * IND + tid];
    float s = v, s2 = v * v;
#pragma unroll
    for (int o = 16; o > 0; o >>= 1) {
        s  += __shfl_xor_sync(0xffffffffu, s,  o);
        s2 += __shfl_xor_sync(0xffffffffu, s2, o);
    }
    __shared__ float sh[2][8];
    int w = tid >> 5, l = tid & 31;
    if (l == 0) { sh[0][w] = s; sh[1][w] = s2; }
    __syncthreads();
    float ts = 0.f, ts2 = 0.f;
#pragma unroll
    for (int i = 0; i < 8; i++) { ts += sh[0][i]; ts2 += sh[1][i]; }
    float mu  = ts * (1.0f / IND);
    float var = ts2 * (1.0f / IND) - mu * mu;
    float r   = rsqrtf(var + 1e-5f);
    g_normed[(size_t)row * IND + tid] = (v - mu) * r * gamma[tid] + beta[tid];
}

// ---------------------------------------------------------------------------
// Prep: all W-independent per-step work (elu+1, sum-norm, sigmoid, k.q),
// rewritten chain-major for the recurrence. One warp per (t, chain).
// ---------------------------------------------------------------------------
__global__ __launch_bounds__(256)
void prep_kernel()
{
    int gw   = blockIdx.x * 8 + (threadIdx.x >> 5);   // 0 .. SLEN*NCHAIN-1
    int lane = threadIdx.x & 31;
    int t    = gw >> 7;
    int ch   = gw & 127;
    int b    = ch >> 3, h = ch & 7;

    const float* base = g_qkvb + ((size_t)t * BSZ + b) * PROJ + h * 97;
    float q = base[lane], k = base[32 + lane], v = base[64 + lane], bta = base[96];

    float eq = q > 0.f ? q + 1.f : __expf(q);
    float ek = k > 0.f ? k + 1.f : __expf(k);
    float sq = eq, sk = ek, sqk = eq * ek;
#pragma unroll
    for (int o = 16; o > 0; o >>= 1) {
        sq  += __shfl_xor_sync(0xffffffffu, sq,  o);
        sk  += __shfl_xor_sync(0xffffffffu, sk,  o);
        sqk += __shfl_xor_sync(0xffffffffu, sqk, o);
    }
    float rsq = 1.0f / (sq + 1e-5f);
    float rsk = 1.0f / (sk + 1e-5f);

    size_t o_idx = ((size_t)ch * SLEN + t) * DH + lane;
    g_qn[o_idx] = eq * rsq;
    g_kn[o_idx] = ek * rsk;
    g_vn[o_idx] = v;
    if (lane == 0) {
        size_t si = ((size_t)ch * SLEN + t) * 2;
        g_sc[si]     = 1.0f / (1.0f + __expf(-bta));
        g_sc[si + 1] = sqk * rsq * rsk;
    }
}

// ---------------------------------------------------------------------------
// Tiled NT GEMM: C[M,N] = A[M,K]*B[N,K]^T (+resid), f32x2 FMA,
// smem double-buffered with register-staged global loads. 1 barrier / tile.
// ---------------------------------------------------------------------------
#define BM 128
#define BN 128
#define BK 16
#define LDS_PAD 132

__global__ __launch_bounds__(256, 2)
void gemm_nt(const float* __restrict__ A, const float* __restrict__ B,
             float* __restrict__ C, int M, int N, int K,
             const float* __restrict__ resid)
{
    __shared__ __align__(16) float As[2][BK][LDS_PAD];
    __shared__ __align__(16) float Bs[2][BK][LDS_PAD];

    int bm = blockIdx.x * BM;
    int bn = blockIdx.y * BN;
    int tid = threadIdx.x;
    int tx = tid & 15, ty = tid >> 4;
    int m0 = ty * 8, n0 = tx * 8;

    int f0 = tid,       r0 = f0 >> 2, kq0 = (f0 & 3) * 4;
    int f1 = tid + 256, r1 = f1 >> 2, kq1 = (f1 & 3) * 4;

    float4 va0, va1, vb0, vb1;

    auto LOAD = [&](int k0) {
        va0 = *(const float4*)(A + (size_t)(bm + r0) * K + k0 + kq0);
        va1 = *(const float4*)(A + (size_t)(bm + r1) * K + k0 + kq1);
        vb0 = make_float4(0.f, 0.f, 0.f, 0.f);
        vb1 = make_float4(0.f, 0.f, 0.f, 0.f);
        if (bn + r0 < N) vb0 = *(const float4*)(B + (size_t)(bn + r0) * K + k0 + kq0);
        if (bn + r1 < N) vb1 = *(const float4*)(B + (size_t)(bn + r1) * K + k0 + kq1);
    };
    auto STORE = [&](int buf) {
        As[buf][kq0 + 0][r0] = va0.x; As[buf][kq0 + 1][r0] = va0.y;
        As[buf][kq0 + 2][r0] = va0.z; As[buf][kq0 + 3][r0] = va0.w;
        As[buf][kq1 + 0][r1] = va1.x; As[buf][kq1 + 1][r1] = va1.y;
        As[buf][kq1 + 2][r1] = va1.z; As[buf][kq1 + 3][r1] = va1.w;
        Bs[buf][kq0 + 0][r0] = vb0.x; Bs[buf][kq0 + 1][r0] = vb0.y;
        Bs[buf][kq0 + 2][r0] = vb0.z; Bs[buf][kq0 + 3][r0] = vb0.w;
        Bs[buf][kq1 + 0][r1] = vb1.x; Bs[buf][kq1 + 1][r1] = vb1.y;
        Bs[buf][kq1 + 2][r1] = vb1.z; Bs[buf][kq1 + 3][r1] = vb1.w;
    };

    u64t acc[8][4];
#pragma unroll
    for (int i = 0; i < 8; i++)
#pragma unroll
        for (int j = 0; j < 4; j++) acc[i][j] = 0ull;

    LOAD(0); STORE(0);
    __syncthreads();

    int nk = K / BK;
    for (int kt = 0; kt < nk; kt++) {
        int cur = kt & 1;
        if (kt + 1 < nk) LOAD((kt + 1) * BK);   // in flight under compute

#pragma unroll
        for (int kk = 0; kk < BK; kk++) {
            float4 a0 = *(const float4*)&As[cur][kk][m0];
            float4 a1 = *(const float4*)&As[cur][kk][m0 + 4];
            const u64t* bp = (const u64t*)&Bs[cur][kk][n0];
            u64t b0 = bp[0], b1 = bp[1], b2 = bp[2], b3 = bp[3];

            u64t as[8];
            as[0] = f2pack(a0.x, a0.x); as[1] = f2pack(a0.y, a0.y);
            as[2] = f2pack(a0.z, a0.z); as[3] = f2pack(a0.w, a0.w);
            as[4] = f2pack(a1.x, a1.x); as[5] = f2pack(a1.y, a1.y);
            as[6] = f2pack(a1.z, a1.z); as[7] = f2pack(a1.w, a1.w);
#pragma unroll
            for (int i = 0; i < 8; i++) {
                acc[i][0] = ffma2(as[i], b0, acc[i][0]);
                acc[i][1] = ffma2(as[i], b1, acc[i][1]);
                acc[i][2] = ffma2(as[i], b2, acc[i][2]);
                acc[i][3] = ffma2(as[i], b3, acc[i][3]);
            }
        }

        if (kt + 1 < nk) STORE(cur ^ 1);  // alt buffer: safe (all warps past kt-1)
        __syncthreads();
    }

#pragma unroll
    for (int i = 0; i < 8; i++) {
        int m = bm + m0 + i;
#pragma unroll
        for (int j = 0; j < 4; j++) {
            float c0, c1;
            f2unpack(acc[i][j], c0, c1);
            int n = bn + n0 + 2 * j;
            if (n < N) {
                float v0 = c0;
                if (resid) v0 += resid[(size_t)m * N + n];
                C[(size_t)m * N + n] = v0;
            }
            if (n + 1 < N) {
                float v1 = c1;
                if (resid) v1 += resid[(size_t)m * N + n + 1];
                C[(size_t)m * N + n + 1] = v1;
            }
        }
    }
}

// ---------------------------------------------------------------------------
// Delta-rule recurrence: one warp per chain, lane = W row.
// All activations pre-normalized by prep_kernel. Time staged through smem in
// chunks of TC steps, double-buffered. No shuffles, no div on the step path.
//   v_old = W.k' ; delta = beta*(v - v_old) ; o = W.q' + delta*(k'.q')
//   W += delta * k'^T
// ---------------------------------------------------------------------------
__global__ __launch_bounds__(32)
void rec_kernel(const float* __restrict__ state,
                float* __restrict__ out_fw, int write_fw)
{
    int chain = blockIdx.x;            // 0..127
    int b = chain >> 3, h = chain & 7;
    int lane = threadIdx.x;

    u64t Wp[16];
    const u64t* st = (const u64t*)(state + ((size_t)chain * DH + lane) * DH);
#pragma unroll
    for (int j = 0; j < 16; j++) Wp[j] = st[j];

    __shared__ __align__(16) float sk[2][TC * DH];
    __shared__ __align__(16) float sq[2][TC * DH];
    __shared__ __align__(16) float sv[2][TC * DH];
    __shared__ __align__(16) float ss[2][TC * 2];

    const float* kb = g_kn + (size_t)chain * SLEN * DH;
    const float* qb = g_qn + (size_t)chain * SLEN * DH;
    const float* vb = g_vn + (size_t)chain * SLEN * DH;
    const float* sb = g_sc + (size_t)chain * SLEN * 2;

    auto REFILL = [&](int cc, int buf) {
        const float4* kp = (const float4*)(kb + (size_t)cc * TC * DH);
        const float4* qp = (const float4*)(qb + (size_t)cc * TC * DH);
        const float4* vp = (const float4*)(vb + (size_t)cc * TC * DH);
#pragma unroll
        for (int j = 0; j < 4; j++) {
            ((float4*)sk[buf])[j * 32 + lane] = kp[j * 32 + lane];
            ((float4*)sq[buf])[j * 32 + lane] = qp[j * 32 + lane];
            ((float4*)sv[buf])[j * 32 + lane] = vp[j * 32 + lane];
        }
        ss[buf][lane] = sb[cc * TC * 2 + lane];
    };

    REFILL(0, 0);
    __syncwarp();

    const int NCC = SLEN / TC;
    for (int cc = 0; cc < NCC; cc++) {
        int buf = cc & 1;
        if (cc + 1 < NCC) REFILL(cc + 1, buf ^ 1);   // lands under compute

#pragma unroll 4
        for (int tt = 0; tt < TC; tt++) {
            const u64t* kp = (const u64t*)&sk[buf][tt * DH];
            const u64t* qp = (const u64t*)&sq[buf][tt * DH];
            u64t kv[16];
#pragma unroll
            for (int j = 0; j < 16; j++) kv[j] = kp[j];

            float vcur = sv[buf][tt * DH + lane];
            float beta = ss[buf][tt * 2];
            float kq   = ss[buf][tt * 2 + 1];
            float bv   = beta * vcur;          // off critical path

            u64t a0 = 0ull, a1 = 0ull, a2 = 0ull, a3 = 0ull;
            u64t c0 = 0ull, c1 = 0ull, c2 = 0ull, c3 = 0ull;
#pragma unroll
            for (int j = 0; j < 4; j++) {
                a0 = ffma2(Wp[4 * j + 0], kv[4 * j + 0], a0);
                a1 = ffma2(Wp[4 * j + 1], kv[4 * j + 1], a1);
                a2 = ffma2(Wp[4 * j + 2], kv[4 * j + 2], a2);
                a3 = ffma2(Wp[4 * j + 3], kv[4 * j + 3], a3);
                c0 = ffma2(Wp[4 * j + 0], qp[4 * j + 0], c0);
                c1 = ffma2(Wp[4 * j + 1], qp[4 * j + 1], c1);
                c2 = ffma2(Wp[4 * j + 2], qp[4 * j + 2], c2);
                c3 = ffma2(Wp[4 * j + 3], qp[4 * j + 3], c3);
            }
            float x0, x1, y0, y1, z0, z1, w0, w1;
            f2unpack(a0, x0, x1); f2unpack(a1, y0, y1);
            f2unpack(a2, z0, z1); f2unpack(a3, w0, w1);
            float v_old = ((x0 + x1) + (y0 + y1)) + ((z0 + z1) + (w0 + w1));

            float delta = fmaf(-beta, v_old, bv);          // beta*(v - v_old)

            f2unpack(c0, x0, x1); f2unpack(c1, y0, y1);
            f2unpack(c2, z0, z1); f2unpack(c3, w0, w1);
            float wq = ((x0 + x1) + (y0 + y1)) + ((z0 + z1) + (w0 + w1));
            float o_out = fmaf(delta, kq, wq);

            int t = cc * TC + tt;
            g_oseq[((size_t)t * BSZ + b) * IND + h * DH + lane] = o_out;

            u64t dd = f2pack(delta, delta);
#pragma unroll
            for (int j = 0; j < 16; j++) Wp[j] = ffma2(dd, kv[j], Wp[j]);
        }
        __syncwarp();
    }

    if (write_fw) {
        u64t* fw = (u64t*)(out_fw + ((size_t)chain * DH + lane) * DH);
#pragma unroll
        for (int j = 0; j < 16; j++) fw[j] = Wp[j];
    }
}

// ---------------------------------------------------------------------------
extern "C" void kernel_launch(void* const* d_in, const int* in_sizes, int n_in,
                              void* d_out, int out_size)
{
    const float* x        = (const float*)d_in[0];
    const float* state    = (const float*)d_in[1];
    const float* W_slow   = (const float*)d_in[2];
    const float* ln_gamma = (const float*)d_in[3];
    const float* ln_beta  = (const float*)d_in[4];
    const float* W_out    = (const float*)d_in[5];
    float* out = (float*)d_out;

    float* normed; cudaGetSymbolAddress((void**)&normed, g_normed);
    float* qkvb;   cudaGetSymbolAddress((void**)&qkvb,   g_qkvb);
    float* oseq;   cudaGetSymbolAddress((void**)&oseq,   g_oseq);

    // 1) LayerNorm
    ln_kernel<<<NTOK, IND>>>(x, ln_gamma, ln_beta);

    // 2) qkvb = normed @ W_slow^T   [16384 x 776]
    dim3 gB(NTOK / BM, (PROJ + BN - 1) / BN);
    gemm_nt<<<gB, 256>>>(normed, W_slow, qkvb, NTOK, PROJ, IND, nullptr);

    // 3) prep: activations + normalizers + beta + k.q, chain-major
    prep_kernel<<<SLEN * NCHAIN / 8, 256>>>();

    // 4) delta-rule recurrence
    int write_fw = (out_size >= (int)((size_t)NTOK * IND + FW_ELEMS)) ? 1 : 0;
    rec_kernel<<<NCHAIN, DH>>>(state, out + (size_t)NTOK * IND, write_fw);

    // 5) out = x + oseq @ W_out^T   [16384 x 256]
    dim3 gD(NTOK / BM, (IND + BN - 1) / BN);
    gemm_nt<<<gD, 256>>>(oseq, W_out, out, NTOK, IND, IND, x);
}

// round 5
// speedup vs baseline: 1.5047x; 1.5047x over previous
#include <cuda_runtime.h>
#include <cstdint>

#define SLEN 1024
#define BSZ  16
#define IND  256
#define NH   8
#define DH   32
#define PROJ 776              // NH*(3*DH+1)
#define NTOK (SLEN*BSZ)       // 16384
#define NCHAIN (BSZ*NH)       // 128
#define FW_ELEMS (NCHAIN*DH*DH)
#define TC   16               // time steps staged per smem refill
#define NCHUNK (SLEN/4)       // 4-step WY chunks per chain

// Scratch (static device globals; no runtime allocation)
__device__ float g_normed[(size_t)NTOK*IND];
__device__ float g_qkvb[(size_t)NTOK*PROJ];
__device__ float g_oseq[(size_t)NTOK*IND];
// chain-major prepped streams: [chain][t][lane]
__device__ float g_kn[(size_t)NCHAIN*SLEN*DH];
__device__ float g_qn[(size_t)NCHAIN*SLEN*DH];
__device__ float g_vn[(size_t)NCHAIN*SLEN*DH];
__device__ float g_sc[(size_t)NCHAIN*SLEN*2];        // (beta, k.q) per step
// WY cross terms per 4-step chunk: [chain][chunk][16]
//   [0..9]  k_i . q_j  for (i,j) in (00,01,02,03,11,12,13,22,23,33)
//   [10..15] -beta_j * (k_i . k_j) for (01,02,03,12,13,23)
__device__ float g_cross[(size_t)NCHAIN*NCHUNK*16];

// ---------------------------------------------------------------------------
// Packed f32x2 helpers (Blackwell)
// ---------------------------------------------------------------------------
typedef unsigned long long u64t;

__device__ __forceinline__ u64t f2pack(float lo, float hi) {
    u64t r;
    asm("mov.b64 %0, {%1, %2};" : "=l"(r) : "f"(lo), "f"(hi));
    return r;
}
__device__ __forceinline__ void f2unpack(u64t v, float& lo, float& hi) {
    asm("mov.b64 {%0, %1}, %2;" : "=f"(lo), "=f"(hi) : "l"(v));
}
__device__ __forceinline__ u64t ffma2(u64t a, u64t b, u64t c) {
    u64t d;
    asm("fma.rn.f32x2 %0, %1, %2, %3;" : "=l"(d) : "l"(a), "l"(b), "l"(c));
    return d;
}

// row-dot: lane-local dot of packed W row with packed vector (2 accum chains)
__device__ __forceinline__ float matvec32(const u64t* __restrict__ Wp,
                                          const u64t* __restrict__ vp) {
    u64t a = 0ull, b = 0ull;
#pragma unroll
    for (int j = 0; j < 8; j++) {
        a = ffma2(Wp[2 * j],     vp[2 * j],     a);
        b = ffma2(Wp[2 * j + 1], vp[2 * j + 1], b);
    }
    float x0, x1, y0, y1;
    f2unpack(a, x0, x1); f2unpack(b, y0, y1);
    return (x0 + y0) + (x1 + y1);
}

// ---------------------------------------------------------------------------
// LayerNorm: one block (256 threads) per token row
// ---------------------------------------------------------------------------
__global__ void ln_kernel(const float* __restrict__ x,
                          const float* __restrict__ gamma,
                          const float* __restrict__ beta)
{
    int row = blockIdx.x;
    int tid = threadIdx.x;
    float v = x[(size_t)row * IND + tid];
    float s = v, s2 = v * v;
#pragma unroll
    for (int o = 16; o > 0; o >>= 1) {
        s  += __shfl_xor_sync(0xffffffffu, s,  o);
        s2 += __shfl_xor_sync(0xffffffffu, s2, o);
    }
    __shared__ float sh[2][8];
    int w = tid >> 5, l = tid & 31;
    if (l == 0) { sh[0][w] = s; sh[1][w] = s2; }
    __syncthreads();
    float ts = 0.f, ts2 = 0.f;
#pragma unroll
    for (int i = 0; i < 8; i++) { ts += sh[0][i]; ts2 += sh[1][i]; }
    float mu  = ts * (1.0f / IND);
    float var = ts2 * (1.0f / IND) - mu * mu;
    float r   = rsqrtf(var + 1e-5f);
    g_normed[(size_t)row * IND + tid] = (v - mu) * r * gamma[tid] + beta[tid];
}

// ---------------------------------------------------------------------------
// Prep: elu+1, sum-norm, sigmoid(beta), k.q — chain-major. One warp / (t,chain)
// ---------------------------------------------------------------------------
__global__ __launch_bounds__(256)
void prep_kernel()
{
    int gw   = blockIdx.x * 8 + (threadIdx.x >> 5);
    int lane = threadIdx.x & 31;
    int t    = gw >> 7;
    int ch   = gw & 127;
    int b    = ch >> 3, h = ch & 7;

    const float* base = g_qkvb + ((size_t)t * BSZ + b) * PROJ + h * 97;
    float q = base[lane], k = base[32 + lane], v = base[64 + lane], bta = base[96];

    float eq = q > 0.f ? q + 1.f : __expf(q);
    float ek = k > 0.f ? k + 1.f : __expf(k);
    float sq = eq, sk = ek, sqk = eq * ek;
#pragma unroll
    for (int o = 16; o > 0; o >>= 1) {
        sq  += __shfl_xor_sync(0xffffffffu, sq,  o);
        sk  += __shfl_xor_sync(0xffffffffu, sk,  o);
        sqk += __shfl_xor_sync(0xffffffffu, sqk, o);
    }
    float rsq = 1.0f / (sq + 1e-5f);
    float rsk = 1.0f / (sk + 1e-5f);

    size_t o_idx = ((size_t)ch * SLEN + t) * DH + lane;
    g_qn[o_idx] = eq * rsq;
    g_kn[o_idx] = ek * rsk;
    g_vn[o_idx] = v;
    if (lane == 0) {
        size_t si = ((size_t)ch * SLEN + t) * 2;
        g_sc[si]     = 1.0f / (1.0f + __expf(-bta));
        g_sc[si + 1] = sqk * rsq * rsk;
    }
}

// ---------------------------------------------------------------------------
// Prep2: WY cross terms per 4-step chunk. One warp per (chain, chunk).
// ---------------------------------------------------------------------------
__global__ __launch_bounds__(256)
void prep2_kernel()
{
    int gw   = blockIdx.x * 8 + (threadIdx.x >> 5);   // 0 .. NCHAIN*NCHUNK-1
    int lane = threadIdx.x & 31;
    int ch   = gw >> 8;          // chain
    int cu   = gw & 255;         // chunk
    int t0   = cu * 4;

    const float* kb = g_kn + ((size_t)ch * SLEN + t0) * DH;
    const float* qb = g_qn + ((size_t)ch * SLEN + t0) * DH;
    float k0 = kb[lane], k1 = kb[DH + lane], k2 = kb[2 * DH + lane], k3 = kb[3 * DH + lane];
    float q0 = qb[lane], q1 = qb[DH + lane], q2 = qb[2 * DH + lane], q3 = qb[3 * DH + lane];

    float r[16];
    r[0]  = k0 * q0; r[1]  = k0 * q1; r[2]  = k0 * q2; r[3]  = k0 * q3;
    r[4]  = k1 * q1; r[5]  = k1 * q2; r[6]  = k1 * q3;
    r[7]  = k2 * q2; r[8]  = k2 * q3; r[9]  = k3 * q3;
    r[10] = k0 * k1; r[11] = k0 * k2; r[12] = k0 * k3;
    r[13] = k1 * k2; r[14] = k1 * k3; r[15] = k2 * k3;
#pragma unroll
    for (int o = 16; o > 0; o >>= 1) {
#pragma unroll
        for (int i = 0; i < 16; i++)
            r[i] += __shfl_xor_sync(0xffffffffu, r[i], o);
    }

    const float* sc = g_sc + ((size_t)ch * SLEN + t0) * 2;
    float b1 = sc[2], b2 = sc[4], b3 = sc[6];
    r[10] *= -b1; r[11] *= -b2; r[12] *= -b3;
    r[13] *= -b2; r[14] *= -b3; r[15] *= -b3;

    if (lane == 0) {
        float4* o = (float4*)(g_cross + ((size_t)ch * NCHUNK + cu) * 16);
        o[0] = make_float4(r[0],  r[1],  r[2],  r[3]);
        o[1] = make_float4(r[4],  r[5],  r[6],  r[7]);
        o[2] = make_float4(r[8],  r[9],  r[10], r[11]);
        o[3] = make_float4(r[12], r[13], r[14], r[15]);
    }
}

// ---------------------------------------------------------------------------
// Tiled NT GEMM: C[M,N] = A[M,K]*B[N,K]^T (+resid), f32x2 FMA,
// double-buffered smem, register-staged loads, NO reg cap (no min-blocks).
// ---------------------------------------------------------------------------
#define BM 128
#define BN 128
#define BK 16
#define LDS_PAD 132

__global__ __launch_bounds__(256)
void gemm_nt(const float* __restrict__ A, const float* __restrict__ B,
             float* __restrict__ C, int M, int N, int K,
             const float* __restrict__ resid)
{
    __shared__ __align__(16) float As[2][BK][LDS_PAD];
    __shared__ __align__(16) float Bs[2][BK][LDS_PAD];

    int bm = blockIdx.x * BM;
    int bn = blockIdx.y * BN;
    int tid = threadIdx.x;
    int tx = tid & 15, ty = tid >> 4;
    int m0 = ty * 8, n0 = tx * 8;

    int f0 = tid,       r0 = f0 >> 2, kq0 = (f0 & 3) * 4;
    int f1 = tid + 256, r1 = f1 >> 2, kq1 = (f1 & 3) * 4;

    float4 va0, va1, vb0, vb1;

    auto LOAD = [&](int k0) {
        va0 = *(const float4*)(A + (size_t)(bm + r0) * K + k0 + kq0);
        va1 = *(const float4*)(A + (size_t)(bm + r1) * K + k0 + kq1);
        vb0 = make_float4(0.f, 0.f, 0.f, 0.f);
        vb1 = make_float4(0.f, 0.f, 0.f, 0.f);
        if (bn + r0 < N) vb0 = *(const float4*)(B + (size_t)(bn + r0) * K + k0 + kq0);
        if (bn + r1 < N) vb1 = *(const float4*)(B + (size_t)(bn + r1) * K + k0 + kq1);
    };
    auto STORE = [&](int buf) {
        As[buf][kq0 + 0][r0] = va0.x; As[buf][kq0 + 1][r0] = va0.y;
        As[buf][kq0 + 2][r0] = va0.z; As[buf][kq0 + 3][r0] = va0.w;
        As[buf][kq1 + 0][r1] = va1.x; As[buf][kq1 + 1][r1] = va1.y;
        As[buf][kq1 + 2][r1] = va1.z; As[buf][kq1 + 3][r1] = va1.w;
        Bs[buf][kq0 + 0][r0] = vb0.x; Bs[buf][kq0 + 1][r0] = vb0.y;
        Bs[buf][kq0 + 2][r0] = vb0.z; Bs[buf][kq0 + 3][r0] = vb0.w;
        Bs[buf][kq1 + 0][r1] = vb1.x; Bs[buf][kq1 + 1][r1] = vb1.y;
        Bs[buf][kq1 + 2][r1] = vb1.z; Bs[buf][kq1 + 3][r1] = vb1.w;
    };

    u64t acc[8][4];
#pragma unroll
    for (int i = 0; i < 8; i++)
#pragma unroll
        for (int j = 0; j < 4; j++) acc[i][j] = 0ull;

    LOAD(0); STORE(0);
    __syncthreads();

    int nk = K / BK;
    for (int kt = 0; kt < nk; kt++) {
        int cur = kt & 1;
        if (kt + 1 < nk) LOAD((kt + 1) * BK);

#pragma unroll
        for (int kk = 0; kk < BK; kk++) {
            float4 a0 = *(const float4*)&As[cur][kk][m0];
            float4 a1 = *(const float4*)&As[cur][kk][m0 + 4];
            const u64t* bp = (const u64t*)&Bs[cur][kk][n0];
            u64t b0 = bp[0], b1 = bp[1], b2 = bp[2], b3 = bp[3];

            u64t as[8];
            as[0] = f2pack(a0.x, a0.x); as[1] = f2pack(a0.y, a0.y);
            as[2] = f2pack(a0.z, a0.z); as[3] = f2pack(a0.w, a0.w);
            as[4] = f2pack(a1.x, a1.x); as[5] = f2pack(a1.y, a1.y);
            as[6] = f2pack(a1.z, a1.z); as[7] = f2pack(a1.w, a1.w);
#pragma unroll
            for (int i = 0; i < 8; i++) {
                acc[i][0] = ffma2(as[i], b0, acc[i][0]);
                acc[i][1] = ffma2(as[i], b1, acc[i][1]);
                acc[i][2] = ffma2(as[i], b2, acc[i][2]);
                acc[i][3] = ffma2(as[i], b3, acc[i][3]);
            }
        }

        if (kt + 1 < nk) STORE(cur ^ 1);
        __syncthreads();
    }

#pragma unroll
    for (int i = 0; i < 8; i++) {
        int m = bm + m0 + i;
#pragma unroll
        for (int j = 0; j < 4; j++) {
            float c0, c1;
            f2unpack(acc[i][j], c0, c1);
            int n = bn + n0 + 2 * j;
            if (n < N) {
                float v0 = c0;
                if (resid) v0 += resid[(size_t)m * N + n];
                C[(size_t)m * N + n] = v0;
            }
            if (n + 1 < N) {
                float v1 = c1;
                if (resid) v1 += resid[(size_t)m * N + n + 1];
                C[(size_t)m * N + n + 1] = v1;
            }
        }
    }
}

// ---------------------------------------------------------------------------
// Delta-rule recurrence, WY-chunked (4 steps per chunk):
//   A_s = W0.k_s, Q_s = W0.q_s  (8 independent matvecs vs same W0)
//   d0 = b0*(v0 - A0); d_j = fma chain using precomputed -b_j*(k_i.k_j)
//   o_j = Q_j + sum_{i<=j} d_i*(k_i.q_j)
//   W  += sum_s d_s k_s^T  (rank-4 batched update)
// One warp per chain, lane = W row. Time staged via double-buffered smem.
// ---------------------------------------------------------------------------
__global__ __launch_bounds__(32)
void rec_kernel(const float* __restrict__ state,
                float* __restrict__ out_fw, int write_fw)
{
    int chain = blockIdx.x;            // 0..127
    int b = chain >> 3, h = chain & 7;
    int lane = threadIdx.x;

    u64t Wp[16];
    const u64t* st = (const u64t*)(state + ((size_t)chain * DH + lane) * DH);
#pragma unroll
    for (int j = 0; j < 16; j++) Wp[j] = st[j];

    __shared__ __align__(16) float sk[2][TC * DH];
    __shared__ __align__(16) float sq[2][TC * DH];
    __shared__ __align__(16) float sv[2][TC * DH];
    __shared__ __align__(16) float sb_[2][TC * 2];
    __shared__ __align__(16) float scr[2][(TC / 4) * 16];  // 64 floats

    const float* kb  = g_kn + (size_t)chain * SLEN * DH;
    const float* qb  = g_qn + (size_t)chain * SLEN * DH;
    const float* vb  = g_vn + (size_t)chain * SLEN * DH;
    const float* sbp = g_sc + (size_t)chain * SLEN * 2;
    const float* crb = g_cross + (size_t)chain * NCHUNK * 16;

    auto REFILL = [&](int cc, int buf) {
        const float4* kp = (const float4*)(kb + (size_t)cc * TC * DH);
        const float4* qp = (const float4*)(qb + (size_t)cc * TC * DH);
        const float4* vp = (const float4*)(vb + (size_t)cc * TC * DH);
#pragma unroll
        for (int j = 0; j < 4; j++) {
            ((float4*)sk[buf])[j * 32 + lane] = kp[j * 32 + lane];
            ((float4*)sq[buf])[j * 32 + lane] = qp[j * 32 + lane];
            ((float4*)sv[buf])[j * 32 + lane] = vp[j * 32 + lane];
        }
        sb_[buf][lane] = sbp[cc * TC * 2 + lane];
        scr[buf][lane]      = crb[cc * 64 + lane];
        scr[buf][32 + lane] = crb[cc * 64 + 32 + lane];
    };

    REFILL(0, 0);
    __syncwarp();

    const int NCC = SLEN / TC;
    for (int cc = 0; cc < NCC; cc++) {
        int buf = cc & 1;
        if (cc + 1 < NCC) REFILL(cc + 1, buf ^ 1);

#pragma unroll
        for (int q4 = 0; q4 < TC / 4; q4++) {
            int tb = q4 * 4;
            const u64t* k0p = (const u64t*)&sk[buf][(tb + 0) * DH];
            const u64t* k1p = (const u64t*)&sk[buf][(tb + 1) * DH];
            const u64t* k2p = (const u64t*)&sk[buf][(tb + 2) * DH];
            const u64t* k3p = (const u64t*)&sk[buf][(tb + 3) * DH];

            // 8 independent matvecs vs W0
            float A0 = matvec32(Wp, k0p);
            float A1 = matvec32(Wp, k1p);
            float A2 = matvec32(Wp, k2p);
            float A3 = matvec32(Wp, k3p);
            float Q0 = matvec32(Wp, (const u64t*)&sq[buf][(tb + 0) * DH]);
            float Q1 = matvec32(Wp, (const u64t*)&sq[buf][(tb + 1) * DH]);
            float Q2 = matvec32(Wp, (const u64t*)&sq[buf][(tb + 2) * DH]);
            float Q3 = matvec32(Wp, (const u64t*)&sq[buf][(tb + 3) * DH]);

            float be0 = sb_[buf][(tb + 0) * 2], be1 = sb_[buf][(tb + 1) * 2];
            float be2 = sb_[buf][(tb + 2) * 2], be3 = sb_[buf][(tb + 3) * 2];
            float vv0 = sv[buf][(tb + 0) * DH + lane];
            float vv1 = sv[buf][(tb + 1) * DH + lane];
            float vv2 = sv[buf][(tb + 2) * DH + lane];
            float vv3 = sv[buf][(tb + 3) * DH + lane];
            const float* cr = &scr[buf][q4 * 16];

            // per-lane delta chain (cr[10..15] already hold -beta_j*kk_ij)
            float d0 = fmaf(-be0, A0, be0 * vv0);
            float p1 = fmaf(-be1, A1, be1 * vv1);
            float p2 = fmaf(-be2, A2, be2 * vv2);
            float p3 = fmaf(-be3, A3, be3 * vv3);
            float d1 = fmaf(d0, cr[10], p1);
            float d2 = fmaf(d1, cr[13], fmaf(d0, cr[11], p2));
            float d3 = fmaf(d2, cr[15], fmaf(d1, cr[14], fmaf(d0, cr[12], p3)));

            // outputs
            float o0 = fmaf(d0, cr[0], Q0);
            float o1 = fmaf(d1, cr[4], fmaf(d0, cr[1], Q1));
            float o2 = fmaf(d2, cr[7], fmaf(d1, cr[5], fmaf(d0, cr[2], Q2)));
            float o3 = fmaf(d3, cr[9], fmaf(d2, cr[8], fmaf(d1, cr[6], fmaf(d0, cr[3], Q3))));

            int t = cc * TC + tb;
            size_t ob = ((size_t)t * BSZ + b) * IND + h * DH + lane;
            g_oseq[ob]                       = o0;
            g_oseq[ob + (size_t)BSZ * IND]     = o1;
            g_oseq[ob + (size_t)2 * BSZ * IND] = o2;
            g_oseq[ob + (size_t)3 * BSZ * IND] = o3;

            // rank-4 W update
            u64t D0 = f2pack(d0, d0), D1 = f2pack(d1, d1);
            u64t D2 = f2pack(d2, d2), D3 = f2pack(d3, d3);
            const ulonglong2* K0 = (const ulonglong2*)k0p;
            const ulonglong2* K1 = (const ulonglong2*)k1p;
            const ulonglong2* K2 = (const ulonglong2*)k2p;
            const ulonglong2* K3 = (const ulonglong2*)k3p;
#pragma unroll
            for (int jj = 0; jj < 8; jj++) {
                ulonglong2 t0 = K0[jj], t1 = K1[jj], t2 = K2[jj], t3 = K3[jj];
                u64t w0 = Wp[2 * jj], w1 = Wp[2 * jj + 1];
                w0 = ffma2(D0, t0.x, w0); w1 = ffma2(D0, t0.y, w1);
                w0 = ffma2(D1, t1.x, w0); w1 = ffma2(D1, t1.y, w1);
                w0 = ffma2(D2, t2.x, w0); w1 = ffma2(D2, t2.y, w1);
                w0 = ffma2(D3, t3.x, w0); w1 = ffma2(D3, t3.y, w1);
                Wp[2 * jj] = w0; Wp[2 * jj + 1] = w1;
            }
        }
        __syncwarp();
    }

    if (write_fw) {
        u64t* fw = (u64t*)(out_fw + ((size_t)chain * DH + lane) * DH);
#pragma unroll
        for (int j = 0; j < 16; j++) fw[j] = Wp[j];
    }
}

// ---------------------------------------------------------------------------
extern "C" void kernel_launch(void* const* d_in, const int* in_sizes, int n_in,
                              void* d_out, int out_size)
{
    const float* x        = (const float*)d_in[0];
    const float* state    = (const float*)d_in[1];
    const float* W_slow   = (const float*)d_in[2];
    const float* ln_gamma = (const float*)d_in[3];
    const float* ln_beta  = (const float*)d_in[4];
    const float* W_out    = (const float*)d_in[5];
    float* out = (float*)d_out;

    float* normed; cudaGetSymbolAddress((void**)&normed, g_normed);
    float* qkvb;   cudaGetSymbolAddress((void**)&qkvb,   g_qkvb);
    float* oseq;   cudaGetSymbolAddress((void**)&oseq,   g_oseq);

    // 1) LayerNorm
    ln_kernel<<<NTOK, IND>>>(x, ln_gamma, ln_beta);

    // 2) qkvb = normed @ W_slow^T   [16384 x 776]
    dim3 gB(NTOK / BM, (PROJ + BN - 1) / BN);
    gemm_nt<<<gB, 256>>>(normed, W_slow, qkvb, NTOK, PROJ, IND, nullptr);

    // 3) prep: activations + normalizers + beta + k.q, chain-major
    prep_kernel<<<SLEN * NCHAIN / 8, 256>>>();

    // 3b) prep2: WY cross terms per 4-step chunk
    prep2_kernel<<<NCHAIN * NCHUNK / 8, 256>>>();

    // 4) delta-rule recurrence (WY-chunked)
    int write_fw = (out_size >= (int)((size_t)NTOK * IND + FW_ELEMS)) ? 1 : 0;
    rec_kernel<<<NCHAIN, DH>>>(state, out + (size_t)NTOK * IND, write_fw);

    // 5) out = x + oseq @ W_out^T   [16384 x 256]
    dim3 gD(NTOK / BM, (IND + BN - 1) / BN);
    gemm_nt<<<gD, 256>>>(oseq, W_out, out, NTOK, IND, IND, x);
}